// round 7
// baseline (speedup 1.0000x reference)
#include <cuda_runtime.h>

// LayerNormSoftmaxChain: x[N,4] -> LN(4) -> @W[4,3] -> softmax(3) -> out[N,3]
// N = 8388608. HBM-streaming: 16B in / 12B out per row (224 MiB total).
//
// R6: R2's proven structure (front-batched LDG.128, MLP=4, smem-staged
// coalesced stores, single kernel) + algebraic param reduction so the fold
// costs only 10 registers (no constant bank, no extra graph nodes):
//   softmax shift-invariance: subtract logit 0  ->  2 logits
//     B[i][j] = gamma[i]*(W[i][j+1]-W[i][0]),  j=0,1
//   LN mean-term folds into weights: B'[i][j] = B[i][j] - mean_i(B[:,j])
//     => l_j = inv * (x . B'_j) + c_j,  c_j = sum_i beta[i]*(W[i][j+1]-W[i][0])
//   out = {1, e^{l0}, e^{l1}} / (1 + e^{l0} + e^{l1})

#define ROWS_PER_BLOCK 1024   // 256 threads * 4 rows

__global__ __launch_bounds__(256, 8)
void lnsm_kernel(const float4* __restrict__ x4,
                 const float* __restrict__ W,
                 const float* __restrict__ gamma,
                 const float* __restrict__ beta,
                 float4* __restrict__ out4)
{
    __shared__ float s[ROWS_PER_BLOCK * 3];   // 12 KB

    const int t = threadIdx.x;
    const float4* xb = x4 + (size_t)blockIdx.x * ROWS_PER_BLOCK;

    // Front-batch 4 coalesced LDG.128 (MLP=4) before anything else.
    float4 v0 = xb[t];
    float4 v1 = xb[t + 256];
    float4 v2 = xb[t + 512];
    float4 v3 = xb[t + 768];

    // Fold params while loads are in flight (broadcast L2-hit loads).
    float B0[4], B1[4];           // raw gamma*(W_j - W_0)
    float c0 = 0.f, c1 = 0.f;
    #pragma unroll
    for (int i = 0; i < 4; i++) {
        float g  = __ldg(gamma + i);
        float b  = __ldg(beta + i);
        float w0 = __ldg(W + i * 3 + 0);
        float w1 = __ldg(W + i * 3 + 1);
        float w2 = __ldg(W + i * 3 + 2);
        float d1 = w1 - w0, d2 = w2 - w0;
        B0[i] = g * d1;
        B1[i] = g * d2;
        c0 = fmaf(b, d1, c0);
        c1 = fmaf(b, d2, c1);
    }
    // Subtract column means so the LN mu-term vanishes: x.B' = (x-mu).B
    float m0 = (B0[0] + B0[1] + B0[2] + B0[3]) * 0.25f;
    float m1 = (B1[0] + B1[1] + B1[2] + B1[3]) * 0.25f;
    #pragma unroll
    for (int i = 0; i < 4; i++) { B0[i] -= m0; B1[i] -= m1; }

    float4 vs[4] = {v0, v1, v2, v3};

    #pragma unroll
    for (int r = 0; r < 4; r++) {
        float4 v = vs[r];

        float sum = (v.x + v.y) + (v.z + v.w);
        float mu  = sum * 0.25f;
        float sq  = fmaf(v.x, v.x, fmaf(v.y, v.y, fmaf(v.z, v.z, v.w * v.w)));
        float var = fmaf(sq, 0.25f, -mu * mu);
        float inv = rsqrtf(var + 1e-5f);

        float d0 = fmaf(v.x, B0[0], fmaf(v.y, B0[1], fmaf(v.z, B0[2], v.w * B0[3])));
        float d1 = fmaf(v.x, B1[0], fmaf(v.y, B1[1], fmaf(v.z, B1[2], v.w * B1[3])));

        float l0 = fmaf(inv, d0, c0);
        float l1 = fmaf(inv, d1, c1);

        // softmax with logit-0 shift: e for lane0 is exactly 1
        float e0 = __expf(l0);
        float e1 = __expf(l1);
        float rs = __fdividef(1.0f, 1.0f + e0 + e1);

        int row = t + 256 * r;
        s[row * 3 + 0] = rs;         // stride-3: coprime with 32 banks
        s[row * 3 + 1] = e0 * rs;
        s[row * 3 + 2] = e1 * rs;
    }

    __syncthreads();

    // Flush 768 float4 per block, perfectly coalesced.
    float4* ob = out4 + (size_t)blockIdx.x * (ROWS_PER_BLOCK * 3 / 4);
    const float4* s4 = (const float4*)s;
    ob[t]       = s4[t];
    ob[t + 256] = s4[t + 256];
    ob[t + 512] = s4[t + 512];
}

extern "C" void kernel_launch(void* const* d_in, const int* in_sizes, int n_in,
                              void* d_out, int out_size)
{
    const float* x     = (const float*)d_in[0];   // [N,4]
    const float* W     = (const float*)d_in[1];   // [4,3]
    const float* gamma = (const float*)d_in[2];   // [4]
    const float* beta  = (const float*)d_in[3];   // [4]
    float* out = (float*)d_out;                   // [N,3]

    int n_rows = in_sizes[0] / 4;
    int blocks = n_rows / ROWS_PER_BLOCK;         // 8192, exact
    lnsm_kernel<<<blocks, 256>>>((const float4*)x, W, gamma, beta, (float4*)out);
}